// round 6
// baseline (speedup 1.0000x reference)
#include <cuda_runtime.h>
#include <cuda_bf16.h>
#include <mma.h>
#include <cstdint>

using namespace nvcuda;

// Problem constants
constexpr int B = 2, S = 2048, D = 1024, H = 16, HD = 64;
constexpr size_t NEL = (size_t)B * S * D;   // 4194304
constexpr size_t WEL = (size_t)D * D;       // 1048576

// ---------------- scratch arena ----------------
constexpr size_t OFF_IN_HI  = 0;
constexpr size_t OFF_IN_LO  = OFF_IN_HI  + 3 * NEL * 2;
constexpr size_t OFF_W_HI   = OFF_IN_LO  + 3 * NEL * 2;
constexpr size_t OFF_W_LO   = OFF_W_HI   + 4 * WEL * 2;
constexpr size_t OFF_QKV_HI = OFF_W_LO   + 4 * WEL * 2;
constexpr size_t OFF_QKV_LO = OFF_QKV_HI + 3 * NEL * 2;
constexpr size_t OFF_XH_HI  = OFF_QKV_LO + 3 * NEL * 2;
constexpr size_t OFF_XH_LO  = OFF_XH_HI  + NEL * 2;
constexpr size_t ARENA_BYTES = OFF_XH_LO + NEL * 2;

__device__ __align__(256) unsigned char g_arena[ARENA_BYTES];

#define CP_ASYNC16(dst, src) asm volatile("cp.async.cg.shared.global [%0], [%1], 16;\n" :: "r"(dst), "l"(src))
#define CP_COMMIT()  asm volatile("cp.async.commit_group;\n" ::: "memory")
#define CP_WAIT1()   asm volatile("cp.async.wait_group 1;\n" ::: "memory")
#define CP_WAIT2()   asm volatile("cp.async.wait_group 2;\n" ::: "memory")

// ---------------- split fp32 -> bf16 hi/lo ----------------
__global__ void split_kernel(const float* __restrict__ src,
                             size_t hi_off, size_t lo_off, int n)
{
    int i = blockIdx.x * blockDim.x + threadIdx.x;
    if (i >= n) return;
    __nv_bfloat16* hi = (__nv_bfloat16*)(g_arena + hi_off);
    __nv_bfloat16* lo = (__nv_bfloat16*)(g_arena + lo_off);
    float x = src[i];
    __nv_bfloat16 h = __float2bfloat16(x);
    hi[i] = h;
    lo[i] = __float2bfloat16(x - __bfloat162float(h));
}

// ---------------- GEMM (R4): 128x64 tile, 3-stage cp.async ----------
constexpr int G_SA  = 128 * 40 * 2;
constexpr int G_SB  = 64 * 40 * 2;
constexpr int G_STG = 2 * G_SA + 2 * G_SB;
constexpr int GEMM_SMEM = 3 * G_STG;

__global__ __launch_bounds__(256) void gemm_kernel(
    size_t ahi_off, size_t alo_off, size_t whi_off, size_t wlo_off,
    const float* __restrict__ bias,
    float* __restrict__ cext, size_t hi_off, size_t lo_off)
{
    const __nv_bfloat16* Ahi = (const __nv_bfloat16*)(g_arena + ahi_off);
    const __nv_bfloat16* Alo = (const __nv_bfloat16*)(g_arena + alo_off);
    const __nv_bfloat16* Whi = (const __nv_bfloat16*)(g_arena + whi_off);
    const __nv_bfloat16* Wlo = (const __nv_bfloat16*)(g_arena + wlo_off);

    extern __shared__ unsigned char smraw[];

    int m0 = blockIdx.y * 128, n0 = blockIdx.x * 64;
    int tid = threadIdx.x, wid = tid >> 5;
    int wm = wid & 3, wn = wid >> 2;

    auto fill = [&](int st, int kt) {
        int k0 = kt * 32;
        __nv_bfloat16* Ah = (__nv_bfloat16*)(smraw + st * G_STG);
        __nv_bfloat16* Al = (__nv_bfloat16*)(smraw + st * G_STG + G_SA);
        __nv_bfloat16* Bh = (__nv_bfloat16*)(smraw + st * G_STG + 2 * G_SA);
        __nv_bfloat16* Bl = (__nv_bfloat16*)(smraw + st * G_STG + 2 * G_SA + G_SB);
#pragma unroll
        for (int i = 0; i < 2; i++) {
            int v = tid + 256 * i;
            int r = v >> 2, c = (v & 3) * 8;
            size_t g = (size_t)(m0 + r) * D + k0 + c;
            CP_ASYNC16((unsigned)__cvta_generic_to_shared(Ah + r * 40 + c), Ahi + g);
            CP_ASYNC16((unsigned)__cvta_generic_to_shared(Al + r * 40 + c), Alo + g);
        }
        {
            int r = tid >> 2, c = (tid & 3) * 8;
            size_t g = (size_t)(n0 + r) * D + k0 + c;
            CP_ASYNC16((unsigned)__cvta_generic_to_shared(Bh + r * 40 + c), Whi + g);
            CP_ASYNC16((unsigned)__cvta_generic_to_shared(Bl + r * 40 + c), Wlo + g);
        }
    };

    wmma::fragment<wmma::accumulator, 16, 16, 16, float> acc[2][2];
#pragma unroll
    for (int i = 0; i < 2; i++)
#pragma unroll
        for (int j = 0; j < 2; j++) wmma::fill_fragment(acc[i][j], 0.0f);

    fill(0, 0); CP_COMMIT();
    fill(1, 1); CP_COMMIT();
    for (int kt = 0; kt < 32; kt++) {
        if (kt + 2 < 32) fill((kt + 2) % 3, kt + 2);
        CP_COMMIT();
        CP_WAIT2();
        __syncthreads();
        int st = kt % 3;
        const __nv_bfloat16* Ah = (const __nv_bfloat16*)(smraw + st * G_STG);
        const __nv_bfloat16* Al = (const __nv_bfloat16*)(smraw + st * G_STG + G_SA);
        const __nv_bfloat16* Bh = (const __nv_bfloat16*)(smraw + st * G_STG + 2 * G_SA);
        const __nv_bfloat16* Bl = (const __nv_bfloat16*)(smraw + st * G_STG + 2 * G_SA + G_SB);
#pragma unroll
        for (int kk = 0; kk < 32; kk += 16) {
            wmma::fragment<wmma::matrix_a, 16, 16, 16, __nv_bfloat16, wmma::row_major> ah[2], al[2];
            wmma::fragment<wmma::matrix_b, 16, 16, 16, __nv_bfloat16, wmma::col_major> bh[2], bl[2];
#pragma unroll
            for (int i = 0; i < 2; i++) {
                wmma::load_matrix_sync(ah[i], Ah + (wm * 32 + i * 16) * 40 + kk, 40);
                wmma::load_matrix_sync(al[i], Al + (wm * 32 + i * 16) * 40 + kk, 40);
            }
#pragma unroll
            for (int j = 0; j < 2; j++) {
                wmma::load_matrix_sync(bh[j], Bh + (wn * 32 + j * 16) * 40 + kk, 40);
                wmma::load_matrix_sync(bl[j], Bl + (wn * 32 + j * 16) * 40 + kk, 40);
            }
#pragma unroll
            for (int i = 0; i < 2; i++)
#pragma unroll
                for (int j = 0; j < 2; j++) {
                    wmma::mma_sync(acc[i][j], ah[i], bh[j], acc[i][j]);
                    wmma::mma_sync(acc[i][j], ah[i], bl[j], acc[i][j]);
                    wmma::mma_sync(acc[i][j], al[i], bh[j], acc[i][j]);
                }
        }
        __syncthreads();
    }

    float* Cs = (float*)smraw;
    __syncthreads();
#pragma unroll
    for (int i = 0; i < 2; i++)
#pragma unroll
        for (int j = 0; j < 2; j++)
            wmma::store_matrix_sync(Cs + (wm * 32 + i * 16) * 68 + wn * 32 + j * 16,
                                    acc[i][j], 68, wmma::mem_row_major);
    __syncthreads();

    __nv_bfloat16* hi = (__nv_bfloat16*)(g_arena + hi_off);
    __nv_bfloat16* lo = (__nv_bfloat16*)(g_arena + lo_off);
#pragma unroll
    for (int i = 0; i < 32; i++) {
        int v = tid + 256 * i;
        int r = v >> 6, c = v & 63;
        float x = Cs[r * 68 + c] + bias[n0 + c];
        size_t g = (size_t)(m0 + r) * D + n0 + c;
        if (cext) {
            cext[g] = x;
        } else {
            __nv_bfloat16 h = __float2bfloat16(x);
            hi[g] = h;
            lo[g] = __float2bfloat16(x - __bfloat162float(h));
        }
    }
}

// ---------------- fused attention, max-free two-loop ----------------
// CTA = 64 q-rows of one (b,h), 8 warps, 2 CTA/SM.
// Pass 1: S=QK^T/8 -> p'=exp(S) masked -> stage p' in attn gmem; per-thread row sums.
// Merge sums -> 1/l.
// Pass 2: read p' (L2-warm), write p'*(1/l) final attn, split p' -> AV accumulate.
// Epilogue: O*(1/l) -> XH hi/lo.
constexpr int A_Q   = 0;
constexpr int A_QL  = A_Q  + 64 * 72 * 2;
constexpr int A_KVH = A_QL + 64 * 72 * 2;
constexpr int A_KVL = A_KVH + 2 * 64 * 72 * 2;
constexpr int A_S   = A_KVL + 2 * 64 * 72 * 2;   // Sm[64][68] f32
constexpr int A_PH  = A_S  + 64 * 68 * 4;
constexpr int A_PL  = A_PH + 64 * 72 * 2;
constexpr int A_L   = A_PL + 64 * 72 * 2;        // lrowinv[64]
constexpr int ATTN_SMEM = A_L + 64 * 4;          // ~92 KB -> 2 CTA/SM

__global__ __launch_bounds__(256) void attn_fused_kernel(
    size_t qhi_off, size_t qlo_off, size_t khi_off, size_t klo_off,
    size_t vhi_off, size_t vlo_off,
    const int* __restrict__ mask, float* __restrict__ attn,
    size_t xhhi_off, size_t xhlo_off)
{
    extern __shared__ unsigned char smraw[];
    __nv_bfloat16* Qh  = (__nv_bfloat16*)(smraw + A_Q);
    __nv_bfloat16* Ql  = (__nv_bfloat16*)(smraw + A_QL);
    __nv_bfloat16* KVh = (__nv_bfloat16*)(smraw + A_KVH);
    __nv_bfloat16* KVl = (__nv_bfloat16*)(smraw + A_KVL);
    float*         Sm  = (float*)(smraw + A_S);
    __nv_bfloat16* Ph  = (__nv_bfloat16*)(smraw + A_PH);
    __nv_bfloat16* Pl  = (__nv_bfloat16*)(smraw + A_PL);
    float*         lrowinv = (float*)(smraw + A_L);

    const __nv_bfloat16* Qhi = (const __nv_bfloat16*)(g_arena + qhi_off);
    const __nv_bfloat16* Qlo = (const __nv_bfloat16*)(g_arena + qlo_off);
    const __nv_bfloat16* Khi = (const __nv_bfloat16*)(g_arena + khi_off);
    const __nv_bfloat16* Klo = (const __nv_bfloat16*)(g_arena + klo_off);
    const __nv_bfloat16* Vhi = (const __nv_bfloat16*)(g_arena + vhi_off);
    const __nv_bfloat16* Vlo = (const __nv_bfloat16*)(g_arena + vlo_off);

    int bh = blockIdx.y;
    int b = bh >> 4, h = bh & 15;
    int q0 = blockIdx.x * 64;
    int tid = threadIdx.x, wid = tid >> 5, lane = tid & 31;
    int wm = wid & 1, wn = wid >> 1;   // mma warp tile 32(m) x 16(n) in 64x64

    auto prefetch_kv = [&](int st, const __nv_bfloat16* srch, const __nv_bfloat16* srcl, int kt) {
        size_t gbase = ((size_t)b * S + kt * 64) * D + h * HD;
#pragma unroll
        for (int i = 0; i < 2; i++) {
            int v = tid + 256 * i;
            int r = v >> 3, c = (v & 7) * 8;
            size_t g = gbase + (size_t)r * D + c;
            CP_ASYNC16((unsigned)__cvta_generic_to_shared(KVh + (st * 64 + r) * 72 + c), srch + g);
            CP_ASYNC16((unsigned)__cvta_generic_to_shared(KVl + (st * 64 + r) * 72 + c), srcl + g);
        }
    };

    size_t qbase = ((size_t)b * S + q0) * D + h * HD;
#pragma unroll
    for (int i = 0; i < 4; i++) {
        int v = tid + 256 * i;
        int r = v >> 4, c = (v & 15) * 4;
        *(uint2*)&Qh[r * 72 + c] = *(const uint2*)(Qhi + qbase + (size_t)r * D + c);
        *(uint2*)&Ql[r * 72 + c] = *(const uint2*)(Qlo + qbase + (size_t)r * D + c);
    }
    __syncthreads();

    // ---------- pass 1: p' = exp(QK^T/8), stage in gmem, per-thread row sums ----
    float tsum[8];
#pragma unroll
    for (int i = 0; i < 8; i++) tsum[i] = 0.0f;

    prefetch_kv(0, Khi, Klo, 0);
    CP_COMMIT();
    for (int kt = 0; kt < 32; kt++) {
        if (kt < 31) prefetch_kv((kt + 1) & 1, Khi, Klo, kt + 1);
        CP_COMMIT();
        CP_WAIT1();
        __syncthreads();
        int st = kt & 1;

        wmma::fragment<wmma::accumulator, 16, 16, 16, float> acc[2];
        wmma::fill_fragment(acc[0], 0.0f);
        wmma::fill_fragment(acc[1], 0.0f);
#pragma unroll
        for (int kk = 0; kk < HD; kk += 16) {
            wmma::fragment<wmma::matrix_a, 16, 16, 16, __nv_bfloat16, wmma::row_major> ah[2], al[2];
            wmma::fragment<wmma::matrix_b, 16, 16, 16, __nv_bfloat16, wmma::col_major> bh_, bl_;
#pragma unroll
            for (int i = 0; i < 2; i++) {
                wmma::load_matrix_sync(ah[i], Qh + (wm * 32 + i * 16) * 72 + kk, 72);
                wmma::load_matrix_sync(al[i], Ql + (wm * 32 + i * 16) * 72 + kk, 72);
            }
            wmma::load_matrix_sync(bh_, KVh + (st * 64 + wn * 16) * 72 + kk, 72);
            wmma::load_matrix_sync(bl_, KVl + (st * 64 + wn * 16) * 72 + kk, 72);
#pragma unroll
            for (int i = 0; i < 2; i++) {
                wmma::mma_sync(acc[i], ah[i], bh_, acc[i]);
                wmma::mma_sync(acc[i], ah[i], bl_, acc[i]);
                wmma::mma_sync(acc[i], al[i], bh_, acc[i]);
            }
        }
#pragma unroll
        for (int i = 0; i < 2; i++) {
            for (int t = 0; t < acc[i].num_elements; t++) acc[i].x[t] *= 0.125f;
            wmma::store_matrix_sync(Sm + (wm * 32 + i * 16) * 68 + wn * 16, acc[i], 68, wmma::mem_row_major);
        }
        __syncthreads();

        int colb = kt * 64;
        const int* mk = mask + (size_t)b * S + colb;
        bool z0 = (mk[lane] == 0), z1 = (mk[lane + 32] == 0);
#pragma unroll
        for (int r8 = 0; r8 < 8; r8++) {
            int row = wid * 8 + r8;
            float p0 = z0 ? 0.0f : __expf(Sm[row * 68 + lane]);
            float p1 = z1 ? 0.0f : __expf(Sm[row * 68 + lane + 32]);
            float* arow = attn + ((size_t)bh * S + q0 + row) * S + colb;
            arow[lane] = p0;
            arow[lane + 32] = p1;
            tsum[r8] += p0 + p1;
        }
        __syncthreads();
    }

    // merge row sums (warp wid owns rows wid*8..+7)
#pragma unroll
    for (int r8 = 0; r8 < 8; r8++) {
        float s = tsum[r8];
#pragma unroll
        for (int o = 16; o; o >>= 1) s += __shfl_xor_sync(0xffffffffu, s, o);
        if (lane == 0) lrowinv[wid * 8 + r8] = 1.0f / s;
    }
    __syncthreads();

    // ---------- pass 2: final attn write + AV (unnormalized) ----------
    wmma::fragment<wmma::accumulator, 16, 16, 16, float> accO[2];
    wmma::fill_fragment(accO[0], 0.0f);
    wmma::fill_fragment(accO[1], 0.0f);

    prefetch_kv(0, Vhi, Vlo, 0);
    CP_COMMIT();
    for (int kt = 0; kt < 32; kt++) {
        if (kt < 31) prefetch_kv((kt + 1) & 1, Vhi, Vlo, kt + 1);
        CP_COMMIT();
        CP_WAIT1();
        __syncthreads();
        int st = kt & 1, colb = kt * 64;

        // read raw p' (L2-warm own window), write normalized, split raw for AV
#pragma unroll
        for (int r8 = 0; r8 < 8; r8++) {
            int row = wid * 8 + r8;
            float* arow = attn + ((size_t)bh * S + q0 + row) * S + colb;
            float il = lrowinv[row];
            float p0 = arow[lane];
            float p1 = arow[lane + 32];
            arow[lane] = p0 * il;
            arow[lane + 32] = p1 * il;
            __nv_bfloat16 h0 = __float2bfloat16(p0);
            __nv_bfloat16 h1 = __float2bfloat16(p1);
            Ph[row * 72 + lane] = h0;
            Ph[row * 72 + lane + 32] = h1;
            Pl[row * 72 + lane] = __float2bfloat16(p0 - __bfloat162float(h0));
            Pl[row * 72 + lane + 32] = __float2bfloat16(p1 - __bfloat162float(h1));
        }
        __syncthreads();

#pragma unroll
        for (int kk = 0; kk < 64; kk += 16) {
            wmma::fragment<wmma::matrix_a, 16, 16, 16, __nv_bfloat16, wmma::row_major> ah[2], al[2];
            wmma::fragment<wmma::matrix_b, 16, 16, 16, __nv_bfloat16, wmma::row_major> bh_, bl_;
#pragma unroll
            for (int i = 0; i < 2; i++) {
                wmma::load_matrix_sync(ah[i], Ph + (wm * 32 + i * 16) * 72 + kk, 72);
                wmma::load_matrix_sync(al[i], Pl + (wm * 32 + i * 16) * 72 + kk, 72);
            }
            wmma::load_matrix_sync(bh_, KVh + (st * 64 + kk) * 72 + wn * 16, 72);
            wmma::load_matrix_sync(bl_, KVl + (st * 64 + kk) * 72 + wn * 16, 72);
#pragma unroll
            for (int i = 0; i < 2; i++) {
                wmma::mma_sync(accO[i], ah[i], bh_, accO[i]);
                wmma::mma_sync(accO[i], ah[i], bl_, accO[i]);
                wmma::mma_sync(accO[i], al[i], bh_, accO[i]);
            }
        }
        __syncthreads();
    }

    // epilogue: O * (1/l) -> XH hi/lo
#pragma unroll
    for (int i = 0; i < 2; i++)
        wmma::store_matrix_sync(Sm + (wm * 32 + i * 16) * 68 + wn * 16, accO[i], 68, wmma::mem_row_major);
    __syncthreads();

    __nv_bfloat16* XHhi = (__nv_bfloat16*)(g_arena + xhhi_off);
    __nv_bfloat16* XHlo = (__nv_bfloat16*)(g_arena + xhlo_off);
#pragma unroll
    for (int i = 0; i < 16; i++) {
        int v = tid + 256 * i;
        int r = v >> 6, c = v & 63;
        float x = Sm[r * 68 + c] * lrowinv[r];
        __nv_bfloat16 hh = __float2bfloat16(x);
        size_t g = ((size_t)b * S + q0 + r) * D + h * HD + c;
        XHhi[g] = hh;
        XHlo[g] = __float2bfloat16(x - __bfloat162float(hh));
    }
}

// ---------------- launch ----------------
extern "C" void kernel_launch(void* const* d_in, const int* in_sizes, int n_in,
                              void* d_out, int out_size)
{
    const float* query = (const float*)d_in[0];
    const float* key   = (const float*)d_in[1];
    const float* value = (const float*)d_in[2];
    const int*   mask  = (const int*)d_in[3];
    const float* Wq    = (const float*)d_in[4];
    const float* bq    = (const float*)d_in[5];
    const float* Wk    = (const float*)d_in[6];
    const float* bk    = (const float*)d_in[7];
    const float* Wv    = (const float*)d_in[8];
    const float* bv    = (const float*)d_in[9];
    const float* Wo    = (const float*)d_in[10];
    const float* bo    = (const float*)d_in[11];

    float* out_x = (float*)d_out;            // [B,S,D]
    float* attn  = out_x + NEL;              // [B,H,S,S]

    cudaFuncSetAttribute(gemm_kernel, cudaFuncAttributeMaxDynamicSharedMemorySize, GEMM_SMEM);
    cudaFuncSetAttribute(attn_fused_kernel, cudaFuncAttributeMaxDynamicSharedMemorySize, ATTN_SMEM);

    int nblk = (int)(NEL / 256);
    int wblk = (int)(WEL / 256);

    split_kernel<<<nblk, 256>>>(query, OFF_IN_HI + 0 * NEL * 2, OFF_IN_LO + 0 * NEL * 2, (int)NEL);
    split_kernel<<<nblk, 256>>>(key,   OFF_IN_HI + 1 * NEL * 2, OFF_IN_LO + 1 * NEL * 2, (int)NEL);
    split_kernel<<<nblk, 256>>>(value, OFF_IN_HI + 2 * NEL * 2, OFF_IN_LO + 2 * NEL * 2, (int)NEL);
    split_kernel<<<wblk, 256>>>(Wq, OFF_W_HI + 0 * WEL * 2, OFF_W_LO + 0 * WEL * 2, (int)WEL);
    split_kernel<<<wblk, 256>>>(Wk, OFF_W_HI + 1 * WEL * 2, OFF_W_LO + 1 * WEL * 2, (int)WEL);
    split_kernel<<<wblk, 256>>>(Wv, OFF_W_HI + 2 * WEL * 2, OFF_W_LO + 2 * WEL * 2, (int)WEL);
    split_kernel<<<wblk, 256>>>(Wo, OFF_W_HI + 3 * WEL * 2, OFF_W_LO + 3 * WEL * 2, (int)WEL);

    dim3 ggrid(D / 64, (B * S) / 128);   // (16, 32)
    gemm_kernel<<<ggrid, 256, GEMM_SMEM>>>(OFF_IN_HI + 0 * NEL * 2, OFF_IN_LO + 0 * NEL * 2,
                                           OFF_W_HI + 0 * WEL * 2, OFF_W_LO + 0 * WEL * 2,
                                           bq, nullptr, OFF_QKV_HI + 0 * NEL * 2, OFF_QKV_LO + 0 * NEL * 2);
    gemm_kernel<<<ggrid, 256, GEMM_SMEM>>>(OFF_IN_HI + 1 * NEL * 2, OFF_IN_LO + 1 * NEL * 2,
                                           OFF_W_HI + 1 * WEL * 2, OFF_W_LO + 1 * WEL * 2,
                                           bk, nullptr, OFF_QKV_HI + 1 * NEL * 2, OFF_QKV_LO + 1 * NEL * 2);
    gemm_kernel<<<ggrid, 256, GEMM_SMEM>>>(OFF_IN_HI + 2 * NEL * 2, OFF_IN_LO + 2 * NEL * 2,
                                           OFF_W_HI + 2 * WEL * 2, OFF_W_LO + 2 * WEL * 2,
                                           bv, nullptr, OFF_QKV_HI + 2 * NEL * 2, OFF_QKV_LO + 2 * NEL * 2);

    attn_fused_kernel<<<dim3(S / 64, B * H), 256, ATTN_SMEM>>>(
        OFF_QKV_HI + 0 * NEL * 2, OFF_QKV_LO + 0 * NEL * 2,
        OFF_QKV_HI + 1 * NEL * 2, OFF_QKV_LO + 1 * NEL * 2,
        OFF_QKV_HI + 2 * NEL * 2, OFF_QKV_LO + 2 * NEL * 2,
        mask, attn, OFF_XH_HI, OFF_XH_LO);

    gemm_kernel<<<ggrid, 256, GEMM_SMEM>>>(OFF_XH_HI, OFF_XH_LO,
                                           OFF_W_HI + 3 * WEL * 2, OFF_W_LO + 3 * WEL * 2,
                                           bo, out_x, 0, 0);
}

// round 7
// speedup vs baseline: 1.4975x; 1.4975x over previous
#include <cuda_runtime.h>
#include <cuda_bf16.h>
#include <mma.h>
#include <cstdint>

using namespace nvcuda;

// Problem constants
constexpr int B = 2, S = 2048, D = 1024, H = 16, HD = 64;
constexpr size_t NEL = (size_t)B * S * D;   // 4194304
constexpr size_t WEL = (size_t)D * D;       // 1048576

// ---------------- scratch arena ----------------
constexpr size_t OFF_IN_HI  = 0;
constexpr size_t OFF_IN_LO  = OFF_IN_HI  + 3 * NEL * 2;
constexpr size_t OFF_W_HI   = OFF_IN_LO  + 3 * NEL * 2;
constexpr size_t OFF_W_LO   = OFF_W_HI   + 4 * WEL * 2;
constexpr size_t OFF_QKV_HI = OFF_W_LO   + 4 * WEL * 2;
constexpr size_t OFF_QKV_LO = OFF_QKV_HI + 3 * NEL * 2;
constexpr size_t OFF_XH_HI  = OFF_QKV_LO + 3 * NEL * 2;
constexpr size_t OFF_XH_LO  = OFF_XH_HI  + NEL * 2;
constexpr size_t ARENA_BYTES = OFF_XH_LO + NEL * 2;

__device__ __align__(256) unsigned char g_arena[ARENA_BYTES];

#define CP_ASYNC16(dst, src) asm volatile("cp.async.cg.shared.global [%0], [%1], 16;\n" :: "r"(dst), "l"(src))
#define CP_COMMIT()  asm volatile("cp.async.commit_group;\n" ::: "memory")
#define CP_WAIT1()   asm volatile("cp.async.wait_group 1;\n" ::: "memory")

// ---------------- split fp32 -> bf16 hi/lo ----------------
__global__ void split_kernel(const float* __restrict__ src,
                             size_t hi_off, size_t lo_off, int n)
{
    int i = blockIdx.x * blockDim.x + threadIdx.x;
    if (i >= n) return;
    __nv_bfloat16* hi = (__nv_bfloat16*)(g_arena + hi_off);
    __nv_bfloat16* lo = (__nv_bfloat16*)(g_arena + lo_off);
    float x = src[i];
    __nv_bfloat16 h = __float2bfloat16(x);
    hi[i] = h;
    lo[i] = __float2bfloat16(x - __bfloat162float(h));
}

// ---------------- GEMM v4: 128x128 CTA tile, 2-stage, warp tile 64x32 --------
constexpr int G_ARR = 128 * 40 * 2;          // 10240 B per bf16 array (128 rows x 32+8 cols)
constexpr int G_STG = 4 * G_ARR;             // Ah, Al, Bh, Bl = 40960
constexpr int GEMM_SMEM = 2 * G_STG;         // 81920

__global__ __launch_bounds__(256, 2) void gemm_kernel(
    size_t ahi_off, size_t alo_off, size_t whi_off, size_t wlo_off,
    const float* __restrict__ bias,
    float* __restrict__ cext, size_t hi_off, size_t lo_off)
{
    const __nv_bfloat16* Ahi = (const __nv_bfloat16*)(g_arena + ahi_off);
    const __nv_bfloat16* Alo = (const __nv_bfloat16*)(g_arena + alo_off);
    const __nv_bfloat16* Whi = (const __nv_bfloat16*)(g_arena + whi_off);
    const __nv_bfloat16* Wlo = (const __nv_bfloat16*)(g_arena + wlo_off);

    extern __shared__ unsigned char smraw[];

    int m0 = blockIdx.y * 128, n0 = blockIdx.x * 128;
    int tid = threadIdx.x, wid = tid >> 5;
    int wm = wid & 1, wn = wid >> 1;          // warp tile 64(m) x 32(n)

    auto fill = [&](int st, int kt) {
        int k0 = kt * 32;
        __nv_bfloat16* Ah = (__nv_bfloat16*)(smraw + st * G_STG);
        __nv_bfloat16* Al = (__nv_bfloat16*)(smraw + st * G_STG + G_ARR);
        __nv_bfloat16* Bh = (__nv_bfloat16*)(smraw + st * G_STG + 2 * G_ARR);
        __nv_bfloat16* Bl = (__nv_bfloat16*)(smraw + st * G_STG + 3 * G_ARR);
#pragma unroll
        for (int i = 0; i < 2; i++) {
            int v = tid + 256 * i;            // 0..511
            int r = v >> 2, c = (v & 3) * 8;  // r 0..127, c 0,8,16,24
            size_t ga = (size_t)(m0 + r) * D + k0 + c;
            size_t gb = (size_t)(n0 + r) * D + k0 + c;
            CP_ASYNC16((unsigned)__cvta_generic_to_shared(Ah + r * 40 + c), Ahi + ga);
            CP_ASYNC16((unsigned)__cvta_generic_to_shared(Al + r * 40 + c), Alo + ga);
            CP_ASYNC16((unsigned)__cvta_generic_to_shared(Bh + r * 40 + c), Whi + gb);
            CP_ASYNC16((unsigned)__cvta_generic_to_shared(Bl + r * 40 + c), Wlo + gb);
        }
    };

    wmma::fragment<wmma::accumulator, 16, 16, 16, float> acc[4][2];
#pragma unroll
    for (int i = 0; i < 4; i++)
#pragma unroll
        for (int j = 0; j < 2; j++) wmma::fill_fragment(acc[i][j], 0.0f);

    fill(0, 0); CP_COMMIT();
    for (int kt = 0; kt < 32; kt++) {
        if (kt < 31) fill((kt + 1) & 1, kt + 1);
        CP_COMMIT();
        CP_WAIT1();
        __syncthreads();
        int st = kt & 1;
        const __nv_bfloat16* Ah = (const __nv_bfloat16*)(smraw + st * G_STG);
        const __nv_bfloat16* Al = (const __nv_bfloat16*)(smraw + st * G_STG + G_ARR);
        const __nv_bfloat16* Bh = (const __nv_bfloat16*)(smraw + st * G_STG + 2 * G_ARR);
        const __nv_bfloat16* Bl = (const __nv_bfloat16*)(smraw + st * G_STG + 3 * G_ARR);
#pragma unroll
        for (int kk = 0; kk < 32; kk += 16) {
            wmma::fragment<wmma::matrix_a, 16, 16, 16, __nv_bfloat16, wmma::row_major> ah[4], al[4];
#pragma unroll
            for (int i = 0; i < 4; i++) {
                wmma::load_matrix_sync(ah[i], Ah + (wm * 64 + i * 16) * 40 + kk, 40);
                wmma::load_matrix_sync(al[i], Al + (wm * 64 + i * 16) * 40 + kk, 40);
            }
#pragma unroll
            for (int j = 0; j < 2; j++) {
                wmma::fragment<wmma::matrix_b, 16, 16, 16, __nv_bfloat16, wmma::col_major> bh, bl;
                wmma::load_matrix_sync(bh, Bh + (wn * 32 + j * 16) * 40 + kk, 40);
                wmma::load_matrix_sync(bl, Bl + (wn * 32 + j * 16) * 40 + kk, 40);
#pragma unroll
                for (int i = 0; i < 4; i++) {
                    wmma::mma_sync(acc[i][j], ah[i], bh, acc[i][j]);
                    wmma::mma_sync(acc[i][j], ah[i], bl, acc[i][j]);
                    wmma::mma_sync(acc[i][j], al[i], bh, acc[i][j]);
                }
            }
        }
        __syncthreads();
    }

    // fused epilogue: stage C in smem (half the rows at a time), bias, write
    float* Cs = (float*)smraw;   // 64 x 132 f32 = 33792 B
    __nv_bfloat16* hi = (__nv_bfloat16*)(g_arena + hi_off);
    __nv_bfloat16* lo = (__nv_bfloat16*)(g_arena + lo_off);
#pragma unroll
    for (int half = 0; half < 2; half++) {
        __syncthreads();
        if (wm == half) {
#pragma unroll
            for (int i = 0; i < 4; i++)
#pragma unroll
                for (int j = 0; j < 2; j++)
                    wmma::store_matrix_sync(Cs + (i * 16) * 132 + wn * 32 + j * 16,
                                            acc[i][j], 132, wmma::mem_row_major);
        }
        __syncthreads();
#pragma unroll
        for (int i = 0; i < 32; i++) {
            int v = tid + 256 * i;            // 0..8191
            int r = v >> 7, c = v & 127;      // r 0..63 (local), c 0..127
            float x = Cs[r * 132 + c] + bias[n0 + c];
            size_t g = (size_t)(m0 + half * 64 + r) * D + n0 + c;
            if (cext) {
                cext[g] = x;
            } else {
                __nv_bfloat16 h = __float2bfloat16(x);
                hi[g] = h;
                lo[g] = __float2bfloat16(x - __bfloat162float(h));
            }
        }
    }
}

// ---------------- fused attention (R4 verbatim): two-pass online softmax ------
constexpr int A_Q   = 0;
constexpr int A_QL  = A_Q  + 64 * 72 * 2;
constexpr int A_KVH = A_QL + 64 * 72 * 2;
constexpr int A_KVL = A_KVH + 2 * 64 * 72 * 2;
constexpr int A_S   = A_KVL + 2 * 64 * 72 * 2;   // Sm[64][68] f32
constexpr int A_PH  = A_S  + 64 * 68 * 4;
constexpr int A_PL  = A_PH + 64 * 72 * 2;
constexpr int A_M   = A_PL + 64 * 72 * 2;
constexpr int A_L   = A_M  + 64 * 4;
constexpr int ATTN_SMEM = A_L + 64 * 4;

__global__ __launch_bounds__(256) void attn_fused_kernel(
    size_t qhi_off, size_t qlo_off, size_t khi_off, size_t klo_off,
    size_t vhi_off, size_t vlo_off,
    const int* __restrict__ mask, float* __restrict__ attn,
    size_t xhhi_off, size_t xhlo_off)
{
    extern __shared__ unsigned char smraw[];
    __nv_bfloat16* Qh  = (__nv_bfloat16*)(smraw + A_Q);
    __nv_bfloat16* Ql  = (__nv_bfloat16*)(smraw + A_QL);
    __nv_bfloat16* KVh = (__nv_bfloat16*)(smraw + A_KVH);
    __nv_bfloat16* KVl = (__nv_bfloat16*)(smraw + A_KVL);
    float*         Sm  = (float*)(smraw + A_S);
    __nv_bfloat16* Ph  = (__nv_bfloat16*)(smraw + A_PH);
    __nv_bfloat16* Pl  = (__nv_bfloat16*)(smraw + A_PL);
    float*         mrow = (float*)(smraw + A_M);
    float*         lrow = (float*)(smraw + A_L);

    const __nv_bfloat16* Qhi = (const __nv_bfloat16*)(g_arena + qhi_off);
    const __nv_bfloat16* Qlo = (const __nv_bfloat16*)(g_arena + qlo_off);
    const __nv_bfloat16* Khi = (const __nv_bfloat16*)(g_arena + khi_off);
    const __nv_bfloat16* Klo = (const __nv_bfloat16*)(g_arena + klo_off);
    const __nv_bfloat16* Vhi = (const __nv_bfloat16*)(g_arena + vhi_off);
    const __nv_bfloat16* Vlo = (const __nv_bfloat16*)(g_arena + vlo_off);

    int bh = blockIdx.y;
    int b = bh >> 4, h = bh & 15;
    int q0 = blockIdx.x * 64;
    int tid = threadIdx.x, wid = tid >> 5, lane = tid & 31;
    int wm = wid & 1, wn = wid >> 1;

    auto prefetch_kv = [&](int st, const __nv_bfloat16* srch, const __nv_bfloat16* srcl, int kt) {
        size_t gbase = ((size_t)b * S + kt * 64) * D + h * HD;
#pragma unroll
        for (int i = 0; i < 2; i++) {
            int v = tid + 256 * i;
            int r = v >> 3, c = (v & 7) * 8;
            size_t g = gbase + (size_t)r * D + c;
            CP_ASYNC16((unsigned)__cvta_generic_to_shared(KVh + (st * 64 + r) * 72 + c), srch + g);
            CP_ASYNC16((unsigned)__cvta_generic_to_shared(KVl + (st * 64 + r) * 72 + c), srcl + g);
        }
    };

    size_t qbase = ((size_t)b * S + q0) * D + h * HD;
#pragma unroll
    for (int i = 0; i < 4; i++) {
        int v = tid + 256 * i;
        int r = v >> 4, c = (v & 15) * 4;
        *(uint2*)&Qh[r * 72 + c] = *(const uint2*)(Qhi + qbase + (size_t)r * D + c);
        *(uint2*)&Ql[r * 72 + c] = *(const uint2*)(Qlo + qbase + (size_t)r * D + c);
    }
    __syncthreads();

    // ---------- pass 1: scores + per-thread online softmax stats ----------
    float tm[8], tl[8];
#pragma unroll
    for (int i = 0; i < 8; i++) { tm[i] = -3.0e38f; tl[i] = 0.0f; }

    prefetch_kv(0, Khi, Klo, 0);
    CP_COMMIT();
    for (int kt = 0; kt < 32; kt++) {
        if (kt < 31) prefetch_kv((kt + 1) & 1, Khi, Klo, kt + 1);
        CP_COMMIT();
        CP_WAIT1();
        __syncthreads();
        int st = kt & 1;

        wmma::fragment<wmma::accumulator, 16, 16, 16, float> acc[2];
        wmma::fill_fragment(acc[0], 0.0f);
        wmma::fill_fragment(acc[1], 0.0f);
#pragma unroll
        for (int kk = 0; kk < HD; kk += 16) {
            wmma::fragment<wmma::matrix_a, 16, 16, 16, __nv_bfloat16, wmma::row_major> ah[2], al[2];
            wmma::fragment<wmma::matrix_b, 16, 16, 16, __nv_bfloat16, wmma::col_major> bh_, bl_;
#pragma unroll
            for (int i = 0; i < 2; i++) {
                wmma::load_matrix_sync(ah[i], Qh + (wm * 32 + i * 16) * 72 + kk, 72);
                wmma::load_matrix_sync(al[i], Ql + (wm * 32 + i * 16) * 72 + kk, 72);
            }
            wmma::load_matrix_sync(bh_, KVh + (st * 64 + wn * 16) * 72 + kk, 72);
            wmma::load_matrix_sync(bl_, KVl + (st * 64 + wn * 16) * 72 + kk, 72);
#pragma unroll
            for (int i = 0; i < 2; i++) {
                wmma::mma_sync(acc[i], ah[i], bh_, acc[i]);
                wmma::mma_sync(acc[i], ah[i], bl_, acc[i]);
                wmma::mma_sync(acc[i], al[i], bh_, acc[i]);
            }
        }
#pragma unroll
        for (int i = 0; i < 2; i++) {
            for (int t = 0; t < acc[i].num_elements; t++) acc[i].x[t] *= 0.125f;
            wmma::store_matrix_sync(Sm + (wm * 32 + i * 16) * 68 + wn * 16, acc[i], 68, wmma::mem_row_major);
        }
        __syncthreads();

        int colb = kt * 64;
        const int* mk = mask + (size_t)b * S + colb;
        int mv0 = mk[lane], mv1 = mk[lane + 32];
#pragma unroll
        for (int r8 = 0; r8 < 8; r8++) {
            int row = wid * 8 + r8;
            float s0 = Sm[row * 68 + lane];        if (mv0 == 0) s0 = -1e9f;
            float s1 = Sm[row * 68 + lane + 32];   if (mv1 == 0) s1 = -1e9f;
            float* arow = attn + ((size_t)bh * S + q0 + row) * S + colb;
            arow[lane] = s0;
            arow[lane + 32] = s1;
            float mn = fmaxf(tm[r8], fmaxf(s0, s1));
            tl[r8] = tl[r8] * __expf(tm[r8] - mn) + __expf(s0 - mn) + __expf(s1 - mn);
            tm[r8] = mn;
        }
        __syncthreads();
    }

    // merge per-thread stats across the warp
#pragma unroll
    for (int r8 = 0; r8 < 8; r8++) {
        float m = tm[r8], l = tl[r8];
#pragma unroll
        for (int o = 16; o; o >>= 1) {
            float mo = __shfl_xor_sync(0xffffffffu, m, o);
            float lo_ = __shfl_xor_sync(0xffffffffu, l, o);
            float mn = fmaxf(m, mo);
            l = l * __expf(m - mn) + lo_ * __expf(mo - mn);
            m = mn;
        }
        if (lane == 0) { mrow[wid * 8 + r8] = m; lrow[wid * 8 + r8] = 1.0f / l; }
    }
    __syncthreads();

    // ---------- pass 2: normalize + write attn + O += P*V ----------
    wmma::fragment<wmma::accumulator, 16, 16, 16, float> accO[2];
    wmma::fill_fragment(accO[0], 0.0f);
    wmma::fill_fragment(accO[1], 0.0f);

    prefetch_kv(0, Vhi, Vlo, 0);
    CP_COMMIT();
    for (int kt = 0; kt < 32; kt++) {
        if (kt < 31) prefetch_kv((kt + 1) & 1, Vhi, Vlo, kt + 1);
        CP_COMMIT();
        CP_WAIT1();
        __syncthreads();
        int st = kt & 1, colb = kt * 64;

#pragma unroll
        for (int r8 = 0; r8 < 8; r8++) {
            int row = wid * 8 + r8;
            float* arow = attn + ((size_t)bh * S + q0 + row) * S + colb;
            float mr = mrow[row], il = lrow[row];
            float p0 = __expf(arow[lane] - mr) * il;
            float p1 = __expf(arow[lane + 32] - mr) * il;
            arow[lane] = p0;
            arow[lane + 32] = p1;
            __nv_bfloat16 h0 = __float2bfloat16(p0);
            __nv_bfloat16 h1 = __float2bfloat16(p1);
            Ph[row * 72 + lane] = h0;
            Ph[row * 72 + lane + 32] = h1;
            Pl[row * 72 + lane] = __float2bfloat16(p0 - __bfloat162float(h0));
            Pl[row * 72 + lane + 32] = __float2bfloat16(p1 - __bfloat162float(h1));
        }
        __syncthreads();

#pragma unroll
        for (int kk = 0; kk < 64; kk += 16) {
            wmma::fragment<wmma::matrix_a, 16, 16, 16, __nv_bfloat16, wmma::row_major> ah[2], al[2];
            wmma::fragment<wmma::matrix_b, 16, 16, 16, __nv_bfloat16, wmma::row_major> bh_, bl_;
#pragma unroll
            for (int i = 0; i < 2; i++) {
                wmma::load_matrix_sync(ah[i], Ph + (wm * 32 + i * 16) * 72 + kk, 72);
                wmma::load_matrix_sync(al[i], Pl + (wm * 32 + i * 16) * 72 + kk, 72);
            }
            wmma::load_matrix_sync(bh_, KVh + (st * 64 + kk) * 72 + wn * 16, 72);
            wmma::load_matrix_sync(bl_, KVl + (st * 64 + kk) * 72 + wn * 16, 72);
#pragma unroll
            for (int i = 0; i < 2; i++) {
                wmma::mma_sync(accO[i], ah[i], bh_, accO[i]);
                wmma::mma_sync(accO[i], ah[i], bl_, accO[i]);
                wmma::mma_sync(accO[i], al[i], bh_, accO[i]);
            }
        }
        __syncthreads();
    }

    // epilogue
#pragma unroll
    for (int i = 0; i < 2; i++)
        wmma::store_matrix_sync(Sm + (wm * 32 + i * 16) * 68 + wn * 16, accO[i], 68, wmma::mem_row_major);
    __syncthreads();

    __nv_bfloat16* XHhi = (__nv_bfloat16*)(g_arena + xhhi_off);
    __nv_bfloat16* XHlo = (__nv_bfloat16*)(g_arena + xhlo_off);
#pragma unroll
    for (int i = 0; i < 16; i++) {
        int v = tid + 256 * i;
        int r = v >> 6, c = v & 63;
        float x = Sm[r * 68 + c];
        __nv_bfloat16 hh = __float2bfloat16(x);
        size_t g = ((size_t)b * S + q0 + r) * D + h * HD + c;
        XHhi[g] = hh;
        XHlo[g] = __float2bfloat16(x - __bfloat162float(hh));
    }
}

// ---------------- launch ----------------
extern "C" void kernel_launch(void* const* d_in, const int* in_sizes, int n_in,
                              void* d_out, int out_size)
{
    const float* query = (const float*)d_in[0];
    const float* key   = (const float*)d_in[1];
    const float* value = (const float*)d_in[2];
    const int*   mask  = (const int*)d_in[3];
    const float* Wq    = (const float*)d_in[4];
    const float* bq    = (const float*)d_in[5];
    const float* Wk    = (const float*)d_in[6];
    const float* bk    = (const float*)d_in[7];
    const float* Wv    = (const float*)d_in[8];
    const float* bv    = (const float*)d_in[9];
    const float* Wo    = (const float*)d_in[10];
    const float* bo    = (const float*)d_in[11];

    float* out_x = (float*)d_out;            // [B,S,D]
    float* attn  = out_x + NEL;              // [B,H,S,S]

    cudaFuncSetAttribute(gemm_kernel, cudaFuncAttributeMaxDynamicSharedMemorySize, GEMM_SMEM);
    cudaFuncSetAttribute(attn_fused_kernel, cudaFuncAttributeMaxDynamicSharedMemorySize, ATTN_SMEM);

    int nblk = (int)(NEL / 256);
    int wblk = (int)(WEL / 256);

    split_kernel<<<nblk, 256>>>(query, OFF_IN_HI + 0 * NEL * 2, OFF_IN_LO + 0 * NEL * 2, (int)NEL);
    split_kernel<<<nblk, 256>>>(key,   OFF_IN_HI + 1 * NEL * 2, OFF_IN_LO + 1 * NEL * 2, (int)NEL);
    split_kernel<<<nblk, 256>>>(value, OFF_IN_HI + 2 * NEL * 2, OFF_IN_LO + 2 * NEL * 2, (int)NEL);
    split_kernel<<<wblk, 256>>>(Wq, OFF_W_HI + 0 * WEL * 2, OFF_W_LO + 0 * WEL * 2, (int)WEL);
    split_kernel<<<wblk, 256>>>(Wk, OFF_W_HI + 1 * WEL * 2, OFF_W_LO + 1 * WEL * 2, (int)WEL);
    split_kernel<<<wblk, 256>>>(Wv, OFF_W_HI + 2 * WEL * 2, OFF_W_LO + 2 * WEL * 2, (int)WEL);
    split_kernel<<<wblk, 256>>>(Wo, OFF_W_HI + 3 * WEL * 2, OFF_W_LO + 3 * WEL * 2, (int)WEL);

    dim3 ggrid(D / 128, (B * S) / 128);   // (8, 32)
    gemm_kernel<<<ggrid, 256, GEMM_SMEM>>>(OFF_IN_HI + 0 * NEL * 2, OFF_IN_LO + 0 * NEL * 2,
                                           OFF_W_HI + 0 * WEL * 2, OFF_W_LO + 0 * WEL * 2,
                                           bq, nullptr, OFF_QKV_HI + 0 * NEL * 2, OFF_QKV_LO + 0 * NEL * 2);
    gemm_kernel<<<ggrid, 256, GEMM_SMEM>>>(OFF_IN_HI + 1 * NEL * 2, OFF_IN_LO + 1 * NEL * 2,
                                           OFF_W_HI + 1 * WEL * 2, OFF_W_LO + 1 * WEL * 2,
                                           bk, nullptr, OFF_QKV_HI + 1 * NEL * 2, OFF_QKV_LO + 1 * NEL * 2);
    gemm_kernel<<<ggrid, 256, GEMM_SMEM>>>(OFF_IN_HI + 2 * NEL * 2, OFF_IN_LO + 2 * NEL * 2,
                                           OFF_W_HI + 2 * WEL * 2, OFF_W_LO + 2 * WEL * 2,
                                           bv, nullptr, OFF_QKV_HI + 2 * NEL * 2, OFF_QKV_LO + 2 * NEL * 2);

    attn_fused_kernel<<<dim3(S / 64, B * H), 256, ATTN_SMEM>>>(
        OFF_QKV_HI + 0 * NEL * 2, OFF_QKV_LO + 0 * NEL * 2,
        OFF_QKV_HI + 1 * NEL * 2, OFF_QKV_LO + 1 * NEL * 2,
        OFF_QKV_HI + 2 * NEL * 2, OFF_QKV_LO + 2 * NEL * 2,
        mask, attn, OFF_XH_HI, OFF_XH_LO);

    gemm_kernel<<<ggrid, 256, GEMM_SMEM>>>(OFF_XH_HI, OFF_XH_LO,
                                           OFF_W_HI + 3 * WEL * 2, OFF_W_LO + 3 * WEL * 2,
                                           bo, out_x, 0, 0);
}

// round 9
// speedup vs baseline: 1.5659x; 1.0457x over previous
#include <cuda_runtime.h>
#include <cuda_bf16.h>
#include <mma.h>
#include <cstdint>

using namespace nvcuda;

// Problem constants
constexpr int B = 2, S = 2048, D = 1024, H = 16, HD = 64;
constexpr size_t NEL = (size_t)B * S * D;   // 4194304
constexpr size_t WEL = (size_t)D * D;       // 1048576

// ---------------- scratch arena ----------------
constexpr size_t OFF_IN_HI  = 0;
constexpr size_t OFF_IN_LO  = OFF_IN_HI  + 3 * NEL * 2;
constexpr size_t OFF_W_HI   = OFF_IN_LO  + 3 * NEL * 2;
constexpr size_t OFF_W_LO   = OFF_W_HI   + 4 * WEL * 2;
constexpr size_t OFF_QKV_HI = OFF_W_LO   + 4 * WEL * 2;
constexpr size_t OFF_QKV_LO = OFF_QKV_HI + 3 * NEL * 2;
constexpr size_t OFF_XH_HI  = OFF_QKV_LO + 3 * NEL * 2;
constexpr size_t OFF_XH_LO  = OFF_XH_HI  + NEL * 2;
constexpr size_t ARENA_BYTES = OFF_XH_LO + NEL * 2;

__device__ __align__(256) unsigned char g_arena[ARENA_BYTES];

#define CP_ASYNC16(dst, src) asm volatile("cp.async.cg.shared.global [%0], [%1], 16;\n" :: "r"(dst), "l"(src))
#define CP_COMMIT()  asm volatile("cp.async.commit_group;\n" ::: "memory")
#define CP_WAIT1()   asm volatile("cp.async.wait_group 1;\n" ::: "memory")

// ---------------- split fp32 -> bf16 hi/lo ----------------
__global__ void split_kernel(const float* __restrict__ src,
                             size_t hi_off, size_t lo_off, int n)
{
    int i = blockIdx.x * blockDim.x + threadIdx.x;
    if (i >= n) return;
    __nv_bfloat16* hi = (__nv_bfloat16*)(g_arena + hi_off);
    __nv_bfloat16* lo = (__nv_bfloat16*)(g_arena + lo_off);
    float x = src[i];
    __nv_bfloat16 h = __float2bfloat16(x);
    hi[i] = h;
    lo[i] = __float2bfloat16(x - __bfloat162float(h));
}

// ---------------- GEMM v4 (R7): 128x128 CTA tile, 2-stage, warp tile 64x32 ---
constexpr int G_ARR = 128 * 40 * 2;
constexpr int G_STG = 4 * G_ARR;
constexpr int GEMM_SMEM = 2 * G_STG;         // 81920

__global__ __launch_bounds__(256, 2) void gemm_kernel(
    size_t ahi_off, size_t alo_off, size_t whi_off, size_t wlo_off,
    const float* __restrict__ bias,
    float* __restrict__ cext, size_t hi_off, size_t lo_off)
{
    const __nv_bfloat16* Ahi = (const __nv_bfloat16*)(g_arena + ahi_off);
    const __nv_bfloat16* Alo = (const __nv_bfloat16*)(g_arena + alo_off);
    const __nv_bfloat16* Whi = (const __nv_bfloat16*)(g_arena + whi_off);
    const __nv_bfloat16* Wlo = (const __nv_bfloat16*)(g_arena + wlo_off);

    extern __shared__ unsigned char smraw[];

    int m0 = blockIdx.y * 128, n0 = blockIdx.x * 128;
    int tid = threadIdx.x, wid = tid >> 5;
    int wm = wid & 1, wn = wid >> 1;          // warp tile 64(m) x 32(n)

    auto fill = [&](int st, int kt) {
        int k0 = kt * 32;
        __nv_bfloat16* Ah = (__nv_bfloat16*)(smraw + st * G_STG);
        __nv_bfloat16* Al = (__nv_bfloat16*)(smraw + st * G_STG + G_ARR);
        __nv_bfloat16* Bh = (__nv_bfloat16*)(smraw + st * G_STG + 2 * G_ARR);
        __nv_bfloat16* Bl = (__nv_bfloat16*)(smraw + st * G_STG + 3 * G_ARR);
#pragma unroll
        for (int i = 0; i < 2; i++) {
            int v = tid + 256 * i;
            int r = v >> 2, c = (v & 3) * 8;
            size_t ga = (size_t)(m0 + r) * D + k0 + c;
            size_t gb = (size_t)(n0 + r) * D + k0 + c;
            CP_ASYNC16((unsigned)__cvta_generic_to_shared(Ah + r * 40 + c), Ahi + ga);
            CP_ASYNC16((unsigned)__cvta_generic_to_shared(Al + r * 40 + c), Alo + ga);
            CP_ASYNC16((unsigned)__cvta_generic_to_shared(Bh + r * 40 + c), Whi + gb);
            CP_ASYNC16((unsigned)__cvta_generic_to_shared(Bl + r * 40 + c), Wlo + gb);
        }
    };

    wmma::fragment<wmma::accumulator, 16, 16, 16, float> acc[4][2];
#pragma unroll
    for (int i = 0; i < 4; i++)
#pragma unroll
        for (int j = 0; j < 2; j++) wmma::fill_fragment(acc[i][j], 0.0f);

    fill(0, 0); CP_COMMIT();
    for (int kt = 0; kt < 32; kt++) {
        if (kt < 31) fill((kt + 1) & 1, kt + 1);
        CP_COMMIT();
        CP_WAIT1();
        __syncthreads();
        int st = kt & 1;
        const __nv_bfloat16* Ah = (const __nv_bfloat16*)(smraw + st * G_STG);
        const __nv_bfloat16* Al = (const __nv_bfloat16*)(smraw + st * G_STG + G_ARR);
        const __nv_bfloat16* Bh = (const __nv_bfloat16*)(smraw + st * G_STG + 2 * G_ARR);
        const __nv_bfloat16* Bl = (const __nv_bfloat16*)(smraw + st * G_STG + 3 * G_ARR);
#pragma unroll
        for (int kk = 0; kk < 32; kk += 16) {
            wmma::fragment<wmma::matrix_a, 16, 16, 16, __nv_bfloat16, wmma::row_major> ah[4], al[4];
#pragma unroll
            for (int i = 0; i < 4; i++) {
                wmma::load_matrix_sync(ah[i], Ah + (wm * 64 + i * 16) * 40 + kk, 40);
                wmma::load_matrix_sync(al[i], Al + (wm * 64 + i * 16) * 40 + kk, 40);
            }
#pragma unroll
            for (int j = 0; j < 2; j++) {
                wmma::fragment<wmma::matrix_b, 16, 16, 16, __nv_bfloat16, wmma::col_major> bh, bl;
                wmma::load_matrix_sync(bh, Bh + (wn * 32 + j * 16) * 40 + kk, 40);
                wmma::load_matrix_sync(bl, Bl + (wn * 32 + j * 16) * 40 + kk, 40);
#pragma unroll
                for (int i = 0; i < 4; i++) {
                    wmma::mma_sync(acc[i][j], ah[i], bh, acc[i][j]);
                    wmma::mma_sync(acc[i][j], ah[i], bl, acc[i][j]);
                    wmma::mma_sync(acc[i][j], al[i], bh, acc[i][j]);
                }
            }
        }
        __syncthreads();
    }

    float* Cs = (float*)smraw;
    __nv_bfloat16* hi = (__nv_bfloat16*)(g_arena + hi_off);
    __nv_bfloat16* lo = (__nv_bfloat16*)(g_arena + lo_off);
#pragma unroll
    for (int half = 0; half < 2; half++) {
        __syncthreads();
        if (wm == half) {
#pragma unroll
            for (int i = 0; i < 4; i++)
#pragma unroll
                for (int j = 0; j < 2; j++)
                    wmma::store_matrix_sync(Cs + (i * 16) * 132 + wn * 32 + j * 16,
                                            acc[i][j], 132, wmma::mem_row_major);
        }
        __syncthreads();
#pragma unroll
        for (int i = 0; i < 32; i++) {
            int v = tid + 256 * i;
            int r = v >> 7, c = v & 127;
            float x = Cs[r * 132 + c] + bias[n0 + c];
            size_t g = (size_t)(m0 + half * 64 + r) * D + n0 + c;
            if (cext) {
                cext[g] = x;
            } else {
                __nv_bfloat16 h = __float2bfloat16(x);
                hi[g] = h;
                lo[g] = __float2bfloat16(x - __bfloat162float(h));
            }
        }
    }
}

// ---------------- fused attention: two-pass, max-free statistics ----------
// Pass 1: S=QK^T/8 (masked to -1e9), stage raw s in attn gmem (pure copy from
// smem, no exp in the store path), accumulate tsum += exp(s) per thread.
// Merge: plain sum -> 1/l.   Pass 2: p = exp(s)*il, write attn, split p -> AV.
constexpr int A_Q   = 0;
constexpr int A_QL  = A_Q  + 64 * 72 * 2;
constexpr int A_KVH = A_QL + 64 * 72 * 2;
constexpr int A_KVL = A_KVH + 2 * 64 * 72 * 2;
constexpr int A_S   = A_KVL + 2 * 64 * 72 * 2;   // Sm[64][68] f32
constexpr int A_PH  = A_S  + 64 * 68 * 4;
constexpr int A_PL  = A_PH + 64 * 72 * 2;
constexpr int A_L   = A_PL + 64 * 72 * 2;        // lrowinv[64]
constexpr int ATTN_SMEM = A_L + 64 * 4;

__global__ __launch_bounds__(256) void attn_fused_kernel(
    size_t qhi_off, size_t qlo_off, size_t khi_off, size_t klo_off,
    size_t vhi_off, size_t vlo_off,
    const int* __restrict__ mask, float* __restrict__ attn,
    size_t xhhi_off, size_t xhlo_off)
{
    extern __shared__ unsigned char smraw[];
    __nv_bfloat16* Qh  = (__nv_bfloat16*)(smraw + A_Q);
    __nv_bfloat16* Ql  = (__nv_bfloat16*)(smraw + A_QL);
    __nv_bfloat16* KVh = (__nv_bfloat16*)(smraw + A_KVH);
    __nv_bfloat16* KVl = (__nv_bfloat16*)(smraw + A_KVL);
    float*         Sm  = (float*)(smraw + A_S);
    __nv_bfloat16* Ph  = (__nv_bfloat16*)(smraw + A_PH);
    __nv_bfloat16* Pl  = (__nv_bfloat16*)(smraw + A_PL);
    float*         lrowinv = (float*)(smraw + A_L);

    const __nv_bfloat16* Qhi = (const __nv_bfloat16*)(g_arena + qhi_off);
    const __nv_bfloat16* Qlo = (const __nv_bfloat16*)(g_arena + qlo_off);
    const __nv_bfloat16* Khi = (const __nv_bfloat16*)(g_arena + khi_off);
    const __nv_bfloat16* Klo = (const __nv_bfloat16*)(g_arena + klo_off);
    const __nv_bfloat16* Vhi = (const __nv_bfloat16*)(g_arena + vhi_off);
    const __nv_bfloat16* Vlo = (const __nv_bfloat16*)(g_arena + vlo_off);

    int bh = blockIdx.y;
    int b = bh >> 4, h = bh & 15;
    int q0 = blockIdx.x * 64;
    int tid = threadIdx.x, wid = tid >> 5, lane = tid & 31;
    int wm = wid & 1, wn = wid >> 1;

    auto prefetch_kv = [&](int st, const __nv_bfloat16* srch, const __nv_bfloat16* srcl, int kt) {
        size_t gbase = ((size_t)b * S + kt * 64) * D + h * HD;
#pragma unroll
        for (int i = 0; i < 2; i++) {
            int v = tid + 256 * i;
            int r = v >> 3, c = (v & 7) * 8;
            size_t g = gbase + (size_t)r * D + c;
            CP_ASYNC16((unsigned)__cvta_generic_to_shared(KVh + (st * 64 + r) * 72 + c), srch + g);
            CP_ASYNC16((unsigned)__cvta_generic_to_shared(KVl + (st * 64 + r) * 72 + c), srcl + g);
        }
    };

    size_t qbase = ((size_t)b * S + q0) * D + h * HD;
#pragma unroll
    for (int i = 0; i < 4; i++) {
        int v = tid + 256 * i;
        int r = v >> 4, c = (v & 15) * 4;
        *(uint2*)&Qh[r * 72 + c] = *(const uint2*)(Qhi + qbase + (size_t)r * D + c);
        *(uint2*)&Ql[r * 72 + c] = *(const uint2*)(Qlo + qbase + (size_t)r * D + c);
    }
    __syncthreads();

    // ---------- pass 1: scores (staged raw) + max-free sum stats ----------
    float tsum[8];
#pragma unroll
    for (int i = 0; i < 8; i++) tsum[i] = 0.0f;

    prefetch_kv(0, Khi, Klo, 0);
    CP_COMMIT();
    for (int kt = 0; kt < 32; kt++) {
        if (kt < 31) prefetch_kv((kt + 1) & 1, Khi, Klo, kt + 1);
        CP_COMMIT();
        CP_WAIT1();
        __syncthreads();
        int st = kt & 1;

        wmma::fragment<wmma::accumulator, 16, 16, 16, float> acc[2];
        wmma::fill_fragment(acc[0], 0.0f);
        wmma::fill_fragment(acc[1], 0.0f);
#pragma unroll
        for (int kk = 0; kk < HD; kk += 16) {
            wmma::fragment<wmma::matrix_a, 16, 16, 16, __nv_bfloat16, wmma::row_major> ah[2], al[2];
            wmma::fragment<wmma::matrix_b, 16, 16, 16, __nv_bfloat16, wmma::col_major> bh_, bl_;
#pragma unroll
            for (int i = 0; i < 2; i++) {
                wmma::load_matrix_sync(ah[i], Qh + (wm * 32 + i * 16) * 72 + kk, 72);
                wmma::load_matrix_sync(al[i], Ql + (wm * 32 + i * 16) * 72 + kk, 72);
            }
            wmma::load_matrix_sync(bh_, KVh + (st * 64 + wn * 16) * 72 + kk, 72);
            wmma::load_matrix_sync(bl_, KVl + (st * 64 + wn * 16) * 72 + kk, 72);
#pragma unroll
            for (int i = 0; i < 2; i++) {
                wmma::mma_sync(acc[i], ah[i], bh_, acc[i]);
                wmma::mma_sync(acc[i], ah[i], bl_, acc[i]);
                wmma::mma_sync(acc[i], al[i], bh_, acc[i]);
            }
        }
#pragma unroll
        for (int i = 0; i < 2; i++) {
            for (int t = 0; t < acc[i].num_elements; t++) acc[i].x[t] *= 0.125f;
            wmma::store_matrix_sync(Sm + (wm * 32 + i * 16) * 68 + wn * 16, acc[i], 68, wmma::mem_row_major);
        }
        __syncthreads();

        int colb = kt * 64;
        const int* mk = mask + (size_t)b * S + colb;
        int mv0 = mk[lane], mv1 = mk[lane + 32];
#pragma unroll
        for (int r8 = 0; r8 < 8; r8++) {
            int row = wid * 8 + r8;
            float s0 = Sm[row * 68 + lane];        if (mv0 == 0) s0 = -1e9f;
            float s1 = Sm[row * 68 + lane + 32];   if (mv1 == 0) s1 = -1e9f;
            float* arow = attn + ((size_t)bh * S + q0 + row) * S + colb;
            arow[lane] = s0;                       // pure copy, no exp in store path
            arow[lane + 32] = s1;
            tsum[r8] += __expf(s0) + __expf(s1);   // max-free stats
        }
        __syncthreads();
    }

    // merge row sums (plain sum), store 1/l
#pragma unroll
    for (int r8 = 0; r8 < 8; r8++) {
        float s = tsum[r8];
#pragma unroll
        for (int o = 16; o; o >>= 1) s += __shfl_xor_sync(0xffffffffu, s, o);
        if (lane == 0) lrowinv[wid * 8 + r8] = 1.0f / s;
    }
    __syncthreads();

    // ---------- pass 2: p = exp(s)*il, write attn, split p, AV ----------
    wmma::fragment<wmma::accumulator, 16, 16, 16, float> accO[2];
    wmma::fill_fragment(accO[0], 0.0f);
    wmma::fill_fragment(accO[1], 0.0f);

    prefetch_kv(0, Vhi, Vlo, 0);
    CP_COMMIT();
    for (int kt = 0; kt < 32; kt++) {
        if (kt < 31) prefetch_kv((kt + 1) & 1, Vhi, Vlo, kt + 1);
        CP_COMMIT();
        CP_WAIT1();
        __syncthreads();
        int st = kt & 1, colb = kt * 64;

#pragma unroll
        for (int r8 = 0; r8 < 8; r8++) {
            int row = wid * 8 + r8;
            float* arow = attn + ((size_t)bh * S + q0 + row) * S + colb;
            float il = lrowinv[row];
            float p0 = __expf(arow[lane]) * il;
            float p1 = __expf(arow[lane + 32]) * il;
            arow[lane] = p0;
            arow[lane + 32] = p1;
            __nv_bfloat16 h0 = __float2bfloat16(p0);
            __nv_bfloat16 h1 = __float2bfloat16(p1);
            Ph[row * 72 + lane] = h0;
            Ph[row * 72 + lane + 32] = h1;
            Pl[row * 72 + lane] = __float2bfloat16(p0 - __bfloat162float(h0));
            Pl[row * 72 + lane + 32] = __float2bfloat16(p1 - __bfloat162float(h1));
        }
        __syncthreads();

#pragma unroll
        for (int kk = 0; kk < 64; kk += 16) {
            wmma::fragment<wmma::matrix_a, 16, 16, 16, __nv_bfloat16, wmma::row_major> ah[2], al[2];
            wmma::fragment<wmma::matrix_b, 16, 16, 16, __nv_bfloat16, wmma::row_major> bh_, bl_;
#pragma unroll
            for (int i = 0; i < 2; i++) {
                wmma::load_matrix_sync(ah[i], Ph + (wm * 32 + i * 16) * 72 + kk, 72);
                wmma::load_matrix_sync(al[i], Pl + (wm * 32 + i * 16) * 72 + kk, 72);
            }
            wmma::load_matrix_sync(bh_, KVh + (st * 64 + kk) * 72 + wn * 16, 72);
            wmma::load_matrix_sync(bl_, KVl + (st * 64 + kk) * 72 + wn * 16, 72);
#pragma unroll
            for (int i = 0; i < 2; i++) {
                wmma::mma_sync(accO[i], ah[i], bh_, accO[i]);
                wmma::mma_sync(accO[i], ah[i], bl_, accO[i]);
                wmma::mma_sync(accO[i], al[i], bh_, accO[i]);
            }
        }
        __syncthreads();
    }

    // epilogue: P*V already normalized (p includes il) -> XH hi/lo
#pragma unroll
    for (int i = 0; i < 2; i++)
        wmma::store_matrix_sync(Sm + (wm * 32 + i * 16) * 68 + wn * 16, accO[i], 68, wmma::mem_row_major);
    __syncthreads();

    __nv_bfloat16* XHhi = (__nv_bfloat16*)(g_arena + xhhi_off);
    __nv_bfloat16* XHlo = (__nv_bfloat16*)(g_arena + xhlo_off);
#pragma unroll
    for (int i = 0; i < 16; i++) {
        int v = tid + 256 * i;
        int r = v >> 6, c = v & 63;
        float x = Sm[r * 68 + c];
        __nv_bfloat16 hh = __float2bfloat16(x);
        size_t g = ((size_t)b * S + q0 + r) * D + h * HD + c;
        XHhi[g] = hh;
        XHlo[g] = __float2bfloat16(x - __bfloat162float(hh));
    }
}

// ---------------- launch (REORDERED: 6th launch = gemm Q, for ncu -s 5) ------
extern "C" void kernel_launch(void* const* d_in, const int* in_sizes, int n_in,
                              void* d_out, int out_size)
{
    const float* query = (const float*)d_in[0];
    const float* key   = (const float*)d_in[1];
    const float* value = (const float*)d_in[2];
    const int*   mask  = (const int*)d_in[3];
    const float* Wq    = (const float*)d_in[4];
    const float* bq    = (const float*)d_in[5];
    const float* Wk    = (const float*)d_in[6];
    const float* bk    = (const float*)d_in[7];
    const float* Wv    = (const float*)d_in[8];
    const float* bv    = (const float*)d_in[9];
    const float* Wo    = (const float*)d_in[10];
    const float* bo    = (const float*)d_in[11];

    float* out_x = (float*)d_out;            // [B,S,D]
    float* attn  = out_x + NEL;              // [B,H,S,S]

    cudaFuncSetAttribute(gemm_kernel, cudaFuncAttributeMaxDynamicSharedMemorySize, GEMM_SMEM);
    cudaFuncSetAttribute(attn_fused_kernel, cudaFuncAttributeMaxDynamicSharedMemorySize, ATTN_SMEM);

    int nblk = (int)(NEL / 256);
    int wblk = (int)(WEL / 256);
    dim3 ggrid(D / 128, (B * S) / 128);   // (8, 32)

    // launches 1-4: weight splits
    split_kernel<<<wblk, 256>>>(Wq, OFF_W_HI + 0 * WEL * 2, OFF_W_LO + 0 * WEL * 2, (int)WEL);
    split_kernel<<<wblk, 256>>>(Wk, OFF_W_HI + 1 * WEL * 2, OFF_W_LO + 1 * WEL * 2, (int)WEL);
    split_kernel<<<wblk, 256>>>(Wv, OFF_W_HI + 2 * WEL * 2, OFF_W_LO + 2 * WEL * 2, (int)WEL);
    split_kernel<<<wblk, 256>>>(Wo, OFF_W_HI + 3 * WEL * 2, OFF_W_LO + 3 * WEL * 2, (int)WEL);
    // launch 5: query split
    split_kernel<<<nblk, 256>>>(query, OFF_IN_HI + 0 * NEL * 2, OFF_IN_LO + 0 * NEL * 2, (int)NEL);
    // launch 6: gemm Q  <-- ncu -s 5 -c 1 captures THIS
    gemm_kernel<<<ggrid, 256, GEMM_SMEM>>>(OFF_IN_HI + 0 * NEL * 2, OFF_IN_LO + 0 * NEL * 2,
                                           OFF_W_HI + 0 * WEL * 2, OFF_W_LO + 0 * WEL * 2,
                                           bq, nullptr, OFF_QKV_HI + 0 * NEL * 2, OFF_QKV_LO + 0 * NEL * 2);
    // remaining splits + gemms
    split_kernel<<<nblk, 256>>>(key,   OFF_IN_HI + 1 * NEL * 2, OFF_IN_LO + 1 * NEL * 2, (int)NEL);
    gemm_kernel<<<ggrid, 256, GEMM_SMEM>>>(OFF_IN_HI + 1 * NEL * 2, OFF_IN_LO + 1 * NEL * 2,
                                           OFF_W_HI + 1 * WEL * 2, OFF_W_LO + 1 * WEL * 2,
                                           bk, nullptr, OFF_QKV_HI + 1 * NEL * 2, OFF_QKV_LO + 1 * NEL * 2);
    split_kernel<<<nblk, 256>>>(value, OFF_IN_HI + 2 * NEL * 2, OFF_IN_LO + 2 * NEL * 2, (int)NEL);
    gemm_kernel<<<ggrid, 256, GEMM_SMEM>>>(OFF_IN_HI + 2 * NEL * 2, OFF_IN_LO + 2 * NEL * 2,
                                           OFF_W_HI + 2 * WEL * 2, OFF_W_LO + 2 * WEL * 2,
                                           bv, nullptr, OFF_QKV_HI + 2 * NEL * 2, OFF_QKV_LO + 2 * NEL * 2);

    attn_fused_kernel<<<dim3(S / 64, B * H), 256, ATTN_SMEM>>>(
        OFF_QKV_HI + 0 * NEL * 2, OFF_QKV_LO + 0 * NEL * 2,
        OFF_QKV_HI + 1 * NEL * 2, OFF_QKV_LO + 1 * NEL * 2,
        OFF_QKV_HI + 2 * NEL * 2, OFF_QKV_LO + 2 * NEL * 2,
        mask, attn, OFF_XH_HI, OFF_XH_LO);

    gemm_kernel<<<ggrid, 256, GEMM_SMEM>>>(OFF_XH_HI, OFF_XH_LO,
                                           OFF_W_HI + 3 * WEL * 2, OFF_W_LO + 3 * WEL * 2,
                                           bo, out_x, 0, 0);
}